// round 2
// baseline (speedup 1.0000x reference)
#include <cuda_runtime.h>
#include <math.h>

#define BATCH 256
#define NSTEP 128
#define MSZ   512
#define GSZ   512
#define SLOTS 15
#define SSZ   16

// Scratch (no allocations allowed): qproj[B,n,M] fp32 = 64MB, gproj[B,M].
__device__ float g_qproj[(size_t)BATCH * NSTEP * MSZ];
__device__ float g_gproj[BATCH * MSZ];

// ---------------------------------------------------------------------------
// Kernel 1: gproj[b,m] = attn_b[m] + sum_k gt[b,k] * W[m, 512+k]
// ---------------------------------------------------------------------------
__global__ __launch_bounds__(512) void gproj_kernel(
    const float* __restrict__ gt,
    const float* __restrict__ W,
    const float* __restrict__ bias)
{
    __shared__ float s_gt[GSZ];
    int b = blockIdx.x, tid = threadIdx.x;
    s_gt[tid] = gt[b * GSZ + tid];
    __syncthreads();
    const float4* w4 = (const float4*)(W + (size_t)tid * 1536 + 512);
    const float4* g4 = (const float4*)s_gt;
    float acc = bias[tid];
#pragma unroll 8
    for (int k = 0; k < GSZ / 4; k++) {
        float4 w = w4[k], g = g4[k];
        acc += w.x * g.x + w.y * g.y + w.z * g.z + w.w * g.w;
    }
    g_gproj[b * MSZ + tid] = acc;
}

// ---------------------------------------------------------------------------
// Kernel 2: qproj[r,m] = gproj[b,m] + sum_{k<512} states[r,k] * W[m,k]
// Classic smem-tiled fp32 GEMM: BM=128, BN=64, BK=16, 256 threads, 8x4 micro.
// One row-tile == one batch (BM == NSTEP), so b = blockIdx.y.
// ---------------------------------------------------------------------------
__global__ __launch_bounds__(256) void qproj_gemm(
    const float* __restrict__ X,   // states flat [32768, 512]
    const float* __restrict__ W,   // attn_W [512, 1536]
    float* __restrict__ out)       // g_qproj
{
    __shared__ float As[16][132];  // [k][m], padded stride (16B-aligned rows)
    __shared__ float Bs[16][68];   // [k][n]

    int tid = threadIdx.x;
    int tx = tid & 15;        // n-direction (x4)
    int ty = tid >> 4;        // m-direction (x8)
    int r0 = blockIdx.y * 128;
    int n0 = blockIdx.x * 64;
    int b  = blockIdx.y;

    int lrow = tid >> 2;          // 0..63
    int lkc  = (tid & 3) << 2;    // 0,4,8,12

    float acc[8][4];
#pragma unroll
    for (int a = 0; a < 8; a++)
#pragma unroll
        for (int c = 0; c < 4; c++) acc[a][c] = 0.f;

    for (int k0 = 0; k0 < 512; k0 += 16) {
        float4 a0 = *(const float4*)&X[(size_t)(r0 + lrow) * 512 + k0 + lkc];
        float4 a1 = *(const float4*)&X[(size_t)(r0 + lrow + 64) * 512 + k0 + lkc];
        float4 b0 = *(const float4*)&W[(size_t)(n0 + lrow) * 1536 + k0 + lkc];
        __syncthreads();
        As[lkc + 0][lrow] = a0.x; As[lkc + 1][lrow] = a0.y;
        As[lkc + 2][lrow] = a0.z; As[lkc + 3][lrow] = a0.w;
        As[lkc + 0][lrow + 64] = a1.x; As[lkc + 1][lrow + 64] = a1.y;
        As[lkc + 2][lrow + 64] = a1.z; As[lkc + 3][lrow + 64] = a1.w;
        Bs[lkc + 0][lrow] = b0.x; Bs[lkc + 1][lrow] = b0.y;
        Bs[lkc + 2][lrow] = b0.z; Bs[lkc + 3][lrow] = b0.w;
        __syncthreads();
#pragma unroll
        for (int kk = 0; kk < 16; kk++) {
            float4 ra0 = *(const float4*)&As[kk][ty * 8];
            float4 ra1 = *(const float4*)&As[kk][ty * 8 + 4];
            float4 rb  = *(const float4*)&Bs[kk][tx * 4];
            float av[8] = {ra0.x, ra0.y, ra0.z, ra0.w, ra1.x, ra1.y, ra1.z, ra1.w};
            float bv[4] = {rb.x, rb.y, rb.z, rb.w};
#pragma unroll
            for (int a = 0; a < 8; a++)
#pragma unroll
                for (int c = 0; c < 4; c++)
                    acc[a][c] += av[a] * bv[c];
        }
    }

    const float* gp = g_gproj + b * MSZ + n0 + tx * 4;
    float4 g4 = *(const float4*)gp;
#pragma unroll
    for (int a = 0; a < 8; a++) {
        int r = r0 + ty * 8 + a;
        float4 o;
        o.x = acc[a][0] + g4.x; o.y = acc[a][1] + g4.y;
        o.z = acc[a][2] + g4.z; o.w = acc[a][3] + g4.w;
        *(float4*)(out + (size_t)r * 512 + n0 + tx * 4) = o;
    }
}

// ---------------------------------------------------------------------------
// Kernel 3: sequential writer. One block per batch, 512 threads = 16 warps,
// warp s owns slot s. memproj[b,s,:] lives in registers (16 floats per lane,
// element m = lane + 32*i). Slot 15 (null) is all-zero memproj.
// ---------------------------------------------------------------------------
__global__ __launch_bounds__(512, 2) void writer_kernel(
    const float* __restrict__ his_mem,
    const float* __restrict__ states,
    const float* __restrict__ states_mask,
    const float* __restrict__ gumbel_u,
    const float* __restrict__ attn_W,
    const float* __restrict__ v,
    float* __restrict__ out_hm,
    float* __restrict__ out_log)
{
    __shared__ float s_buf[SLOTS * MSZ];   // hm rows, then memproj staging
    __shared__ float s_q[MSZ];             // qproj row / state row (reused)
    __shared__ float s_row[MSZ];           // recomputed memproj row
    __shared__ float s_e[16];
    __shared__ float s_g[16];
    __shared__ int   s_lastwrite[SLOTS];
    __shared__ int   s_k;
    __shared__ float s_mask;

    int b    = blockIdx.x;
    int tid  = threadIdx.x;
    int lane = tid & 31;
    int warp = tid >> 5;

    float vreg[16];
#pragma unroll
    for (int i = 0; i < 16; i++) vreg[i] = v[lane + 32 * i];

    for (int idx = tid; idx < SLOTS * MSZ; idx += 512)
        s_buf[idx] = his_mem[(size_t)b * SLOTS * MSZ + idx];
    if (tid < SLOTS) s_lastwrite[tid] = -1;
    __syncthreads();

    // memproj init: thread m computes memproj[b,s,m] for all 15 slots.
    {
        float acc[SLOTS];
#pragma unroll
        for (int s = 0; s < SLOTS; s++) acc[s] = 0.f;
        const float4* w4 = (const float4*)(attn_W + (size_t)tid * 1536 + 1024);
        const float4* h4 = (const float4*)s_buf;
        for (int k = 0; k < MSZ / 4; k++) {
            float4 w = w4[k];
#pragma unroll
            for (int s = 0; s < SLOTS; s++) {
                float4 h = h4[s * (MSZ / 4) + k];
                acc[s] += w.x * h.x + w.y * h.y + w.z * h.z + w.w * h.w;
            }
        }
        __syncthreads();
#pragma unroll
        for (int s = 0; s < SLOTS; s++) s_buf[s * MSZ + tid] = acc[s];
        __syncthreads();
    }

    float mp[16];
#pragma unroll
    for (int i = 0; i < 16; i++)
        mp[i] = (warp < SLOTS) ? s_buf[warp * MSZ + lane + 32 * i] : 0.f;

    const float* qrow = g_qproj + (size_t)b * NSTEP * MSZ;

    for (int t = 0; t < NSTEP; t++) {
        s_q[tid] = qrow[t * MSZ + tid];
        if (tid < 16) {
            float u = gumbel_u[((size_t)b * NSTEP + t) * SSZ + tid];
            u = fminf(fmaxf(u, 1e-20f), 1.0f);
            s_g[tid] = -logf(-logf(u) + 1e-20f);
        }
        if (tid == 0) s_mask = states_mask[b * NSTEP + t];
        __syncthreads();

        // energy for this warp's slot
        float p = 0.f;
#pragma unroll
        for (int i = 0; i < 16; i++)
            p += tanhf(s_q[lane + 32 * i] + mp[i]) * vreg[i];
#pragma unroll
        for (int off = 16; off > 0; off >>= 1)
            p += __shfl_xor_sync(0xffffffffu, p, off);
        if (lane == 0) s_e[warp] = p;
        __syncthreads();

        if (warp == 0) {
            float e = (lane < 16) ? s_e[lane] : -1e30f;
            float mx = e;
#pragma unroll
            for (int off = 16; off > 0; off >>= 1)
                mx = fmaxf(mx, __shfl_xor_sync(0xffffffffu, mx, off));
            float ex = expf(e - mx);
            float sm = ex;
#pragma unroll
            for (int off = 16; off > 0; off >>= 1)
                sm += __shfl_xor_sync(0xffffffffu, sm, off);
            float w = ex / sm;
            if (lane == 15) w += 10.0f;   // empty-mask bonus: only null slot
            float z = (lane < 16) ? (w + s_g[lane]) : -1e30f;
            float bz = z; int bi = lane;
#pragma unroll
            for (int off = 16; off > 0; off >>= 1) {
                float oz = __shfl_xor_sync(0xffffffffu, bz, off);
                int   oi = __shfl_xor_sync(0xffffffffu, bi, off);
                if (oz > bz || (oz == bz && oi < bi)) { bz = oz; bi = oi; }
            }
            if (lane < 16)
                out_log[((size_t)b * NSTEP + t) * SSZ + lane] = (lane == bi) ? 1.f : 0.f;
            if (lane == 0)
                s_k = (bi < SLOTS && s_mask != 0.f) ? bi : -1;
        }
        __syncthreads();

        int k = s_k;
        if (k >= 0) {   // rare write event: refresh memproj row k
            s_q[tid] = states[((size_t)b * NSTEP + t) * MSZ + tid];
            if (tid == 0) s_lastwrite[k] = t;
            __syncthreads();
            float acc = 0.f;
            const float4* w4  = (const float4*)(attn_W + (size_t)tid * 1536 + 1024);
            const float4* st4 = (const float4*)s_q;
            for (int kk = 0; kk < MSZ / 4; kk++) {
                float4 w = w4[kk]; float4 s = st4[kk];
                acc += w.x * s.x + w.y * s.y + w.z * s.z + w.w * s.w;
            }
            s_row[tid] = acc;
            __syncthreads();
            if (warp == k) {
#pragma unroll
                for (int i = 0; i < 16; i++) mp[i] = s_row[lane + 32 * i];
            }
            __syncthreads();
        }
    }

    __syncthreads();
    // hm_final: original slot unless written; a written slot equals the state
    // vector from its last write step (hard one-hot write, mask 0/1 exact).
    for (int s = 0; s < SLOTS; s++) {
        int lw = s_lastwrite[s];
        const float* src = (lw >= 0)
            ? (states + ((size_t)b * NSTEP + lw) * MSZ)
            : (his_mem + ((size_t)b * SLOTS + s) * MSZ);
        out_hm[((size_t)b * SLOTS + s) * MSZ + tid] = src[tid];
    }
}

// ---------------------------------------------------------------------------
extern "C" void kernel_launch(void* const* d_in, const int* in_sizes, int n_in,
                              void* d_out, int out_size)
{
    const float* his_mem     = (const float*)d_in[0];
    const float* states      = (const float*)d_in[1];
    const float* states_mask = (const float*)d_in[2];
    const float* gt          = (const float*)d_in[3];
    // d_in[4] = null_mem (all zeros, folded into the constant empty-mask)
    const float* gumbel_u    = (const float*)d_in[5];
    const float* attn_W      = (const float*)d_in[6];
    const float* attn_b      = (const float*)d_in[7];
    const float* v           = (const float*)d_in[8];

    float* out    = (float*)d_out;
    float* out_hm = out;                                    // [B,15,512]
    float* out_log = out + (size_t)BATCH * SLOTS * MSZ;     // [B,128,16]

    float* qproj = nullptr;
    cudaGetSymbolAddress((void**)&qproj, g_qproj);

    gproj_kernel<<<BATCH, 512>>>(gt, attn_W, attn_b);
    dim3 grid_gemm(512 / 64, (BATCH * NSTEP) / 128);
    qproj_gemm<<<grid_gemm, 256>>>(states, attn_W, qproj);
    writer_kernel<<<BATCH, 512>>>(his_mem, states, states_mask, gumbel_u,
                                  attn_W, v, out_hm, out_log);
}

// round 4
// speedup vs baseline: 1.0509x; 1.0509x over previous
#include <cuda_runtime.h>
#include <math.h>
#include <stdint.h>

#define BATCH 256
#define NSTEP 128
#define MSZ   512
#define SLOTS 15
#define SSZ   16

// Scratch (no allocations allowed): qproj[B,n,M] fp32 = 64MB, gproj[B,M].
__device__ float g_qproj[(size_t)BATCH * NSTEP * MSZ];
__device__ float g_gproj[BATCH * MSZ];

// ---------------------------------------------------------------------------
// TF32 helpers
// ---------------------------------------------------------------------------
__device__ __forceinline__ float f2tf(float x) {
    uint32_t r;
    asm("cvt.rna.tf32.f32 %0, %1;" : "=r"(r) : "f"(x));
    return __uint_as_float(r);
}

__device__ __forceinline__ void mma_tf32(float c[4],
                                         uint32_t a0, uint32_t a1,
                                         uint32_t a2, uint32_t a3,
                                         uint32_t b0, uint32_t b1) {
    asm volatile(
        "mma.sync.aligned.m16n8k8.row.col.f32.tf32.tf32.f32 "
        "{%0,%1,%2,%3}, {%4,%5,%6,%7}, {%8,%9}, {%0,%1,%2,%3};"
        : "+f"(c[0]), "+f"(c[1]), "+f"(c[2]), "+f"(c[3])
        : "r"(a0), "r"(a1), "r"(a2), "r"(a3), "r"(b0), "r"(b1));
}

// ---------------------------------------------------------------------------
// Split-TF32 GEMM: out[r, n] = addend[·, n] + sum_k X[r,k] * W[n, wk_off+k]
//   K = 512 always. out row stride = 512. BM=BN=128, BK=32, 256 threads.
//   addend_batched: addend index = blockIdx.y*512 + n (qproj adds gproj[b]);
//   else addend[n] (bias).
//   hi/lo interleaved in smem: row stride 72 floats, [row][2k]=hi, [2k+1]=lo.
// ---------------------------------------------------------------------------
#define BK 32
#define ASTR 72

__global__ __launch_bounds__(256) void tf32_gemm(
    const float* __restrict__ X, int ldx,
    const float* __restrict__ W, int ldw,
    const float* __restrict__ addend, int addend_batched,
    float* __restrict__ out)
{
    __shared__ float sA[128 * ASTR];
    __shared__ float sB[128 * ASTR];
    __shared__ float sAdd[128];

    int tid  = threadIdx.x;
    int warp = tid >> 5, lane = tid & 31;
    int g    = lane >> 2, tig = lane & 3;
    int wm   = (warp >> 2) * 64;   // {0, 64}
    int wn   = (warp & 3) * 32;    // {0,32,64,96}
    int r0   = blockIdx.y * 128;
    int n0   = blockIdx.x * 128;

    if (tid < 128)
        sAdd[tid] = addend[(addend_batched ? blockIdx.y * MSZ : 0) + n0 + tid];

    float acc[4][4][4];
#pragma unroll
    for (int a = 0; a < 4; a++)
#pragma unroll
        for (int b = 0; b < 4; b++)
#pragma unroll
            for (int c = 0; c < 4; c++) acc[a][b][c] = 0.f;

    int lr = tid >> 3;   // 0..31
    int kq = tid & 7;    // 0..7 (float4 column within 32-wide K tile)

    float4 pa[4], pb[4];
#pragma unroll
    for (int i = 0; i < 4; i++) {
        pa[i] = *(const float4*)&X[(size_t)(r0 + lr + 32 * i) * ldx + kq * 4];
        pb[i] = *(const float4*)&W[(size_t)(n0 + lr + 32 * i) * ldw + kq * 4];
    }

    for (int t = 0; t < 512 / BK; t++) {
        __syncthreads();
        // convert + store hi/lo interleaved
#pragma unroll
        for (int i = 0; i < 4; i++) {
            float4 v = pa[i];
            float h0 = f2tf(v.x), h1 = f2tf(v.y), h2 = f2tf(v.z), h3 = f2tf(v.w);
            float4 s0 = {h0, f2tf(v.x - h0), h1, f2tf(v.y - h1)};
            float4 s1 = {h2, f2tf(v.z - h2), h3, f2tf(v.w - h3)};
            float* dst = &sA[(lr + 32 * i) * ASTR + kq * 8];
            *(float4*)dst = s0; *(float4*)(dst + 4) = s1;

            v = pb[i];
            h0 = f2tf(v.x); h1 = f2tf(v.y); h2 = f2tf(v.z); h3 = f2tf(v.w);
            float4 t0 = {h0, f2tf(v.x - h0), h1, f2tf(v.y - h1)};
            float4 t1 = {h2, f2tf(v.z - h2), h3, f2tf(v.w - h3)};
            dst = &sB[(lr + 32 * i) * ASTR + kq * 8];
            *(float4*)dst = t0; *(float4*)(dst + 4) = t1;
        }
        __syncthreads();

        if (t + 1 < 512 / BK) {
            int k0 = (t + 1) * BK;
#pragma unroll
            for (int i = 0; i < 4; i++) {
                pa[i] = *(const float4*)&X[(size_t)(r0 + lr + 32 * i) * ldx + k0 + kq * 4];
                pb[i] = *(const float4*)&W[(size_t)(n0 + lr + 32 * i) * ldw + k0 + kq * 4];
            }
        }

#pragma unroll
        for (int k8 = 0; k8 < BK / 8; k8++) {
            uint32_t Ah[4][4], Al[4][4], Bh[4][2], Bl[4][2];
#pragma unroll
            for (int mf = 0; mf < 4; mf++) {
                int m0 = wm + mf * 16;
                float2 v0 = *(float2*)&sA[(m0 + g)     * ASTR + (k8 * 8 + tig)     * 2];
                float2 v1 = *(float2*)&sA[(m0 + g + 8) * ASTR + (k8 * 8 + tig)     * 2];
                float2 v2 = *(float2*)&sA[(m0 + g)     * ASTR + (k8 * 8 + tig + 4) * 2];
                float2 v3 = *(float2*)&sA[(m0 + g + 8) * ASTR + (k8 * 8 + tig + 4) * 2];
                Ah[mf][0] = __float_as_uint(v0.x); Al[mf][0] = __float_as_uint(v0.y);
                Ah[mf][1] = __float_as_uint(v1.x); Al[mf][1] = __float_as_uint(v1.y);
                Ah[mf][2] = __float_as_uint(v2.x); Al[mf][2] = __float_as_uint(v2.y);
                Ah[mf][3] = __float_as_uint(v3.x); Al[mf][3] = __float_as_uint(v3.y);
            }
#pragma unroll
            for (int nf = 0; nf < 4; nf++) {
                int n = wn + nf * 8 + g;
                float2 v0 = *(float2*)&sB[n * ASTR + (k8 * 8 + tig)     * 2];
                float2 v1 = *(float2*)&sB[n * ASTR + (k8 * 8 + tig + 4) * 2];
                Bh[nf][0] = __float_as_uint(v0.x); Bl[nf][0] = __float_as_uint(v0.y);
                Bh[nf][1] = __float_as_uint(v1.x); Bl[nf][1] = __float_as_uint(v1.y);
            }
#pragma unroll
            for (int mf = 0; mf < 4; mf++)
#pragma unroll
                for (int nf = 0; nf < 4; nf++) {
                    mma_tf32(acc[mf][nf], Ah[mf][0], Ah[mf][1], Ah[mf][2], Ah[mf][3],
                             Bh[nf][0], Bh[nf][1]);
                    mma_tf32(acc[mf][nf], Ah[mf][0], Ah[mf][1], Ah[mf][2], Ah[mf][3],
                             Bl[nf][0], Bl[nf][1]);
                    mma_tf32(acc[mf][nf], Al[mf][0], Al[mf][1], Al[mf][2], Al[mf][3],
                             Bh[nf][0], Bh[nf][1]);
                }
        }
    }

    // epilogue: c0:(g,2tig) c1:(g,2tig+1) c2:(g+8,2tig) c3:(g+8,2tig+1)
#pragma unroll
    for (int mf = 0; mf < 4; mf++)
#pragma unroll
        for (int nf = 0; nf < 4; nf++) {
            int col_l = wn + nf * 8 + 2 * tig;
            int col   = n0 + col_l;
            int row   = r0 + wm + mf * 16 + g;
            float a0 = sAdd[col_l], a1 = sAdd[col_l + 1];
            float2 s0 = {acc[mf][nf][0] + a0, acc[mf][nf][1] + a1};
            float2 s1 = {acc[mf][nf][2] + a0, acc[mf][nf][3] + a1};
            *(float2*)&out[(size_t)row * MSZ + col]       = s0;
            *(float2*)&out[(size_t)(row + 8) * MSZ + col] = s1;
        }
}

// ---------------------------------------------------------------------------
// Sequential writer (unchanged from R2). One block per batch, 16 warps,
// warp s owns slot s; memproj in registers; rare write events recompute row.
// ---------------------------------------------------------------------------
__global__ __launch_bounds__(512, 2) void writer_kernel(
    const float* __restrict__ his_mem,
    const float* __restrict__ states,
    const float* __restrict__ states_mask,
    const float* __restrict__ gumbel_u,
    const float* __restrict__ attn_W,
    const float* __restrict__ v,
    float* __restrict__ out_hm,
    float* __restrict__ out_log)
{
    __shared__ float s_buf[SLOTS * MSZ];
    __shared__ float s_q[MSZ];
    __shared__ float s_row[MSZ];
    __shared__ float s_e[16];
    __shared__ float s_g[16];
    __shared__ int   s_lastwrite[SLOTS];
    __shared__ int   s_k;
    __shared__ float s_mask;

    int b    = blockIdx.x;
    int tid  = threadIdx.x;
    int lane = tid & 31;
    int warp = tid >> 5;

    float vreg[16];
#pragma unroll
    for (int i = 0; i < 16; i++) vreg[i] = v[lane + 32 * i];

    for (int idx = tid; idx < SLOTS * MSZ; idx += 512)
        s_buf[idx] = his_mem[(size_t)b * SLOTS * MSZ + idx];
    if (tid < SLOTS) s_lastwrite[tid] = -1;
    __syncthreads();

    {
        float acc[SLOTS];
#pragma unroll
        for (int s = 0; s < SLOTS; s++) acc[s] = 0.f;
        const float4* w4 = (const float4*)(attn_W + (size_t)tid * 1536 + 1024);
        const float4* h4 = (const float4*)s_buf;
        for (int k = 0; k < MSZ / 4; k++) {
            float4 w = w4[k];
#pragma unroll
            for (int s = 0; s < SLOTS; s++) {
                float4 h = h4[s * (MSZ / 4) + k];
                acc[s] += w.x * h.x + w.y * h.y + w.z * h.z + w.w * h.w;
            }
        }
        __syncthreads();
#pragma unroll
        for (int s = 0; s < SLOTS; s++) s_buf[s * MSZ + tid] = acc[s];
        __syncthreads();
    }

    float mp[16];
#pragma unroll
    for (int i = 0; i < 16; i++)
        mp[i] = (warp < SLOTS) ? s_buf[warp * MSZ + lane + 32 * i] : 0.f;

    const float* qrow = g_qproj + (size_t)b * NSTEP * MSZ;

    for (int t = 0; t < NSTEP; t++) {
        s_q[tid] = qrow[t * MSZ + tid];
        if (tid < 16) {
            float u = gumbel_u[((size_t)b * NSTEP + t) * SSZ + tid];
            u = fminf(fmaxf(u, 1e-20f), 1.0f);
            s_g[tid] = -logf(-logf(u) + 1e-20f);
        }
        if (tid == 0) s_mask = states_mask[b * NSTEP + t];
        __syncthreads();

        float p = 0.f;
#pragma unroll
        for (int i = 0; i < 16; i++)
            p += tanhf(s_q[lane + 32 * i] + mp[i]) * vreg[i];
#pragma unroll
        for (int off = 16; off > 0; off >>= 1)
            p += __shfl_xor_sync(0xffffffffu, p, off);
        if (lane == 0) s_e[warp] = p;
        __syncthreads();

        if (warp == 0) {
            float e = (lane < 16) ? s_e[lane] : -1e30f;
            float mx = e;
#pragma unroll
            for (int off = 16; off > 0; off >>= 1)
                mx = fmaxf(mx, __shfl_xor_sync(0xffffffffu, mx, off));
            float ex = expf(e - mx);
            float sm = ex;
#pragma unroll
            for (int off = 16; off > 0; off >>= 1)
                sm += __shfl_xor_sync(0xffffffffu, sm, off);
            float w = ex / sm;
            if (lane == 15) w += 10.0f;
            float z = (lane < 16) ? (w + s_g[lane]) : -1e30f;
            float bz = z; int bi = lane;
#pragma unroll
            for (int off = 16; off > 0; off >>= 1) {
                float oz = __shfl_xor_sync(0xffffffffu, bz, off);
                int   oi = __shfl_xor_sync(0xffffffffu, bi, off);
                if (oz > bz || (oz == bz && oi < bi)) { bz = oz; bi = oi; }
            }
            if (lane < 16)
                out_log[((size_t)b * NSTEP + t) * SSZ + lane] = (lane == bi) ? 1.f : 0.f;
            if (lane == 0)
                s_k = (bi < SLOTS && s_mask != 0.f) ? bi : -1;
        }
        __syncthreads();

        int k = s_k;
        if (k >= 0) {
            s_q[tid] = states[((size_t)b * NSTEP + t) * MSZ + tid];
            if (tid == 0) s_lastwrite[k] = t;
            __syncthreads();
            float acc = 0.f;
            const float4* w4  = (const float4*)(attn_W + (size_t)tid * 1536 + 1024);
            const float4* st4 = (const float4*)s_q;
            for (int kk = 0; kk < MSZ / 4; kk++) {
                float4 w = w4[kk]; float4 s = st4[kk];
                acc += w.x * s.x + w.y * s.y + w.z * s.z + w.w * s.w;
            }
            s_row[tid] = acc;
            __syncthreads();
            if (warp == k) {
#pragma unroll
                for (int i = 0; i < 16; i++) mp[i] = s_row[lane + 32 * i];
            }
            __syncthreads();
        }
    }

    __syncthreads();
    for (int s = 0; s < SLOTS; s++) {
        int lw = s_lastwrite[s];
        const float* src = (lw >= 0)
            ? (states + ((size_t)b * NSTEP + lw) * MSZ)
            : (his_mem + ((size_t)b * SLOTS + s) * MSZ);
        out_hm[((size_t)b * SLOTS + s) * MSZ + tid] = src[tid];
    }
}

// ---------------------------------------------------------------------------
extern "C" void kernel_launch(void* const* d_in, const int* in_sizes, int n_in,
                              void* d_out, int out_size)
{
    const float* his_mem     = (const float*)d_in[0];
    const float* states      = (const float*)d_in[1];
    const float* states_mask = (const float*)d_in[2];
    const float* gt          = (const float*)d_in[3];
    const float* gumbel_u    = (const float*)d_in[5];
    const float* attn_W      = (const float*)d_in[6];
    const float* attn_b      = (const float*)d_in[7];
    const float* v           = (const float*)d_in[8];

    float* out     = (float*)d_out;
    float* out_hm  = out;                                   // [B,15,512]
    float* out_log = out + (size_t)BATCH * SLOTS * MSZ;     // [B,128,16]

    float* qproj = nullptr;
    float* gproj = nullptr;
    cudaGetSymbolAddress((void**)&qproj, g_qproj);
    cudaGetSymbolAddress((void**)&gproj, g_gproj);

    // gproj[b,m] = bias[m] + gt[b,:] . W[m, 512:1024]
    dim3 grid_g(MSZ / 128, BATCH / 128);
    tf32_gemm<<<grid_g, 256>>>(gt, MSZ, attn_W + 512, 1536, attn_b, 0, gproj);

    // qproj[r,m] = gproj[b,m] + states[r,:] . W[m, 0:512]
    dim3 grid_q(MSZ / 128, (BATCH * NSTEP) / 128);
    tf32_gemm<<<grid_q, 256>>>(states, MSZ, attn_W, 1536, gproj, 1, qproj);

    writer_kernel<<<BATCH, 512>>>(his_mem, states, states_mask, gumbel_u,
                                  attn_W, v, out_hm, out_log);
}

// round 6
// speedup vs baseline: 1.3673x; 1.3011x over previous
#include <cuda_runtime.h>
#include <math.h>
#include <stdint.h>

#define BATCH 256
#define NSTEP 128
#define MSZ   512
#define SLOTS 15
#define SSZ   16

// Scratch (no allocations allowed)
__device__ float g_qproj[(size_t)BATCH * NSTEP * MSZ];    // 64MB
__device__ float g_gproj[BATCH * MSZ];                    // 0.5MB
__device__ float g_memproj[BATCH * SLOTS * MSZ];          // 7.9MB

// ---------------------------------------------------------------------------
// TF32 helpers
// ---------------------------------------------------------------------------
__device__ __forceinline__ float f2tf(float x) {
    uint32_t r;
    asm("cvt.rna.tf32.f32 %0, %1;" : "=r"(r) : "f"(x));
    return __uint_as_float(r);
}

__device__ __forceinline__ void mma_tf32(float c[4],
                                         uint32_t a0, uint32_t a1,
                                         uint32_t a2, uint32_t a3,
                                         uint32_t b0, uint32_t b1) {
    asm volatile(
        "mma.sync.aligned.m16n8k8.row.col.f32.tf32.tf32.f32 "
        "{%0,%1,%2,%3}, {%4,%5,%6,%7}, {%8,%9}, {%0,%1,%2,%3};"
        : "+f"(c[0]), "+f"(c[1]), "+f"(c[2]), "+f"(c[3])
        : "r"(a0), "r"(a1), "r"(a2), "r"(a3), "r"(b0), "r"(b1));
}

// ---------------------------------------------------------------------------
// Unified split-TF32 GEMM. grid = (4, 288):
//   y <  256 : qproj rows  (X=states,  W+0,    out=g_qproj,   no addend)
//   y <  258 : gproj rows  (X=gt,      W+512,  out=g_gproj,   addend=bias)
//   y >= 258 : memproj rows(X=his_mem, W+1024, out=g_memproj, no addend)
// BM=BN=128, BK=32, 256 threads; hi/lo interleaved smem (stride 72).
// ---------------------------------------------------------------------------
#define BK 32
#define ASTR 72

__global__ __launch_bounds__(256) void tf32_gemm_all(
    const float* __restrict__ states,
    const float* __restrict__ gt,
    const float* __restrict__ his_mem,
    const float* __restrict__ W,
    const float* __restrict__ bias,
    float* __restrict__ qproj,
    float* __restrict__ gproj,
    float* __restrict__ memproj)
{
    __shared__ float sA[128 * ASTR];
    __shared__ float sB[128 * ASTR];

    int y = blockIdx.y;
    const float* X;
    const float* Wb;
    const float* addp = nullptr;
    float* outp;
    int r0;
    if (y < 256)      { X = states;  r0 = y * 128;         Wb = W;        outp = qproj; }
    else if (y < 258) { X = gt;      r0 = (y - 256) * 128; Wb = W + 512;  outp = gproj; addp = bias; }
    else              { X = his_mem; r0 = (y - 258) * 128; Wb = W + 1024; outp = memproj; }

    int tid  = threadIdx.x;
    int warp = tid >> 5, lane = tid & 31;
    int g    = lane >> 2, tig = lane & 3;
    int wm   = (warp >> 2) * 64;
    int wn   = (warp & 3) * 32;
    int n0   = blockIdx.x * 128;

    float acc[4][4][4];
#pragma unroll
    for (int a = 0; a < 4; a++)
#pragma unroll
        for (int b = 0; b < 4; b++)
#pragma unroll
            for (int c = 0; c < 4; c++) acc[a][b][c] = 0.f;

    int lr = tid >> 3;
    int kq = tid & 7;

    float4 pa[4], pb[4];
#pragma unroll
    for (int i = 0; i < 4; i++) {
        pa[i] = *(const float4*)&X[(size_t)(r0 + lr + 32 * i) * 512 + kq * 4];
        pb[i] = *(const float4*)&Wb[(size_t)(n0 + lr + 32 * i) * 1536 + kq * 4];
    }

    for (int t = 0; t < 512 / BK; t++) {
        __syncthreads();
#pragma unroll
        for (int i = 0; i < 4; i++) {
            float4 v = pa[i];
            float h0 = f2tf(v.x), h1 = f2tf(v.y), h2 = f2tf(v.z), h3 = f2tf(v.w);
            float4 s0 = {h0, f2tf(v.x - h0), h1, f2tf(v.y - h1)};
            float4 s1 = {h2, f2tf(v.z - h2), h3, f2tf(v.w - h3)};
            float* dst = &sA[(lr + 32 * i) * ASTR + kq * 8];
            *(float4*)dst = s0; *(float4*)(dst + 4) = s1;

            v = pb[i];
            h0 = f2tf(v.x); h1 = f2tf(v.y); h2 = f2tf(v.z); h3 = f2tf(v.w);
            float4 t0 = {h0, f2tf(v.x - h0), h1, f2tf(v.y - h1)};
            float4 t1 = {h2, f2tf(v.z - h2), h3, f2tf(v.w - h3)};
            dst = &sB[(lr + 32 * i) * ASTR + kq * 8];
            *(float4*)dst = t0; *(float4*)(dst + 4) = t1;
        }
        __syncthreads();

        if (t + 1 < 512 / BK) {
            int k0 = (t + 1) * BK;
#pragma unroll
            for (int i = 0; i < 4; i++) {
                pa[i] = *(const float4*)&X[(size_t)(r0 + lr + 32 * i) * 512 + k0 + kq * 4];
                pb[i] = *(const float4*)&Wb[(size_t)(n0 + lr + 32 * i) * 1536 + k0 + kq * 4];
            }
        }

#pragma unroll
        for (int k8 = 0; k8 < BK / 8; k8++) {
            uint32_t Ah[4][4], Al[4][4], Bh[4][2], Bl[4][2];
#pragma unroll
            for (int mf = 0; mf < 4; mf++) {
                int m0 = wm + mf * 16;
                float2 v0 = *(float2*)&sA[(m0 + g)     * ASTR + (k8 * 8 + tig)     * 2];
                float2 v1 = *(float2*)&sA[(m0 + g + 8) * ASTR + (k8 * 8 + tig)     * 2];
                float2 v2 = *(float2*)&sA[(m0 + g)     * ASTR + (k8 * 8 + tig + 4) * 2];
                float2 v3 = *(float2*)&sA[(m0 + g + 8) * ASTR + (k8 * 8 + tig + 4) * 2];
                Ah[mf][0] = __float_as_uint(v0.x); Al[mf][0] = __float_as_uint(v0.y);
                Ah[mf][1] = __float_as_uint(v1.x); Al[mf][1] = __float_as_uint(v1.y);
                Ah[mf][2] = __float_as_uint(v2.x); Al[mf][2] = __float_as_uint(v2.y);
                Ah[mf][3] = __float_as_uint(v3.x); Al[mf][3] = __float_as_uint(v3.y);
            }
#pragma unroll
            for (int nf = 0; nf < 4; nf++) {
                int n = wn + nf * 8 + g;
                float2 v0 = *(float2*)&sB[n * ASTR + (k8 * 8 + tig)     * 2];
                float2 v1 = *(float2*)&sB[n * ASTR + (k8 * 8 + tig + 4) * 2];
                Bh[nf][0] = __float_as_uint(v0.x); Bl[nf][0] = __float_as_uint(v0.y);
                Bh[nf][1] = __float_as_uint(v1.x); Bl[nf][1] = __float_as_uint(v1.y);
            }
#pragma unroll
            for (int mf = 0; mf < 4; mf++)
#pragma unroll
                for (int nf = 0; nf < 4; nf++) {
                    mma_tf32(acc[mf][nf], Ah[mf][0], Ah[mf][1], Ah[mf][2], Ah[mf][3],
                             Bh[nf][0], Bh[nf][1]);
                    mma_tf32(acc[mf][nf], Ah[mf][0], Ah[mf][1], Ah[mf][2], Ah[mf][3],
                             Bl[nf][0], Bl[nf][1]);
                    mma_tf32(acc[mf][nf], Al[mf][0], Al[mf][1], Al[mf][2], Al[mf][3],
                             Bh[nf][0], Bh[nf][1]);
                }
        }
    }

#pragma unroll
    for (int mf = 0; mf < 4; mf++)
#pragma unroll
        for (int nf = 0; nf < 4; nf++) {
            int col_l = wn + nf * 8 + 2 * tig;
            int col   = n0 + col_l;
            int row   = r0 + wm + mf * 16 + g;
            float a0 = 0.f, a1 = 0.f;
            if (addp) { a0 = addp[col]; a1 = addp[col + 1]; }
            float2 s0 = {acc[mf][nf][0] + a0, acc[mf][nf][1] + a1};
            float2 s1 = {acc[mf][nf][2] + a0, acc[mf][nf][3] + a1};
            *(float2*)&outp[(size_t)row * MSZ + col]       = s0;
            *(float2*)&outp[(size_t)(row + 8) * MSZ + col] = s1;
        }
}

// ---------------------------------------------------------------------------
// Exact-enough branch-free tanh: 1 - 2*rcp(exp2(2*log2(e)*x) + 1).
// abs err ~2.4e-7 (ex2/rcp approx ~1-2 ulp) — 100x inside decision margins.
// ---------------------------------------------------------------------------
__device__ __forceinline__ float tanh_acc(float x) {
    float e;
    asm("ex2.approx.f32 %0, %1;" : "=f"(e) : "f"(x * 2.88539008177793f));
    float r;
    asm("rcp.approx.f32 %0, %1;" : "=f"(r) : "f"(e + 1.0f));
    return fmaf(-2.0f, r, 1.0f);
}

// ---------------------------------------------------------------------------
// Sequential writer. One block per batch, 16 warps, warp s owns slot s.
// memproj rows come precomputed from the GEMM; gumbel noise + masks
// precomputed once; q row double-buffered with register prefetch; redundant
// softmax/argmax in every warp (bit-identical) -> 2 syncs per step.
// ---------------------------------------------------------------------------
__global__ __launch_bounds__(512, 2) void writer_kernel(
    const float* __restrict__ his_mem,
    const float* __restrict__ states,
    const float* __restrict__ states_mask,
    const float* __restrict__ gumbel_u,
    const float* __restrict__ attn_W,
    const float* __restrict__ v,
    const float* __restrict__ qproj,
    const float* __restrict__ gproj,
    const float* __restrict__ memproj,
    float* __restrict__ out_hm,
    float* __restrict__ out_log)
{
    __shared__ float s_q[2][MSZ];
    __shared__ float s_v[MSZ];
    __shared__ float s_g[NSTEP][SSZ];
    __shared__ float s_mask[NSTEP];
    __shared__ float s_e[SSZ];
    __shared__ float s_tmp[MSZ];
    __shared__ float s_row[MSZ];
    __shared__ int   s_lastwrite[SLOTS];

    int b    = blockIdx.x;
    int tid  = threadIdx.x;
    int lane = tid & 31;
    int warp = tid >> 5;

    s_v[tid] = v[tid];
    if (tid < SLOTS) s_lastwrite[tid] = -1;
    if (tid < NSTEP) s_mask[tid] = states_mask[b * NSTEP + tid];
    {
        float4 u4 = *(const float4*)(gumbel_u + (size_t)b * NSTEP * SSZ + tid * 4);
        float uu[4] = {u4.x, u4.y, u4.z, u4.w};
        float gg[4];
#pragma unroll
        for (int i = 0; i < 4; i++) {
            float u = fminf(fmaxf(uu[i], 1e-20f), 1.0f);
            gg[i] = -logf(-logf(u) + 1e-20f);
        }
        *(float4*)(&s_g[0][0] + tid * 4) = make_float4(gg[0], gg[1], gg[2], gg[3]);
    }

    float gadd = gproj[b * MSZ + tid];
    float mp[16];
#pragma unroll
    for (int i = 0; i < 16; i++)
        mp[i] = (warp < SLOTS)
              ? memproj[((size_t)b * SLOTS + warp) * MSZ + lane + 32 * i] : 0.f;

    const float* qrow = qproj + (size_t)b * NSTEP * MSZ;
    s_q[0][tid] = qrow[tid] + gadd;
    __syncthreads();

    for (int t = 0; t < NSTEP; t++) {
        int cur = t & 1;
        float qn = 0.f;
        if (t + 1 < NSTEP) qn = qrow[(t + 1) * MSZ + tid];   // prefetch

        float p = 0.f;
#pragma unroll
        for (int i = 0; i < 16; i++) {
            int m = lane + 32 * i;
            p += tanh_acc(s_q[cur][m] + mp[i]) * s_v[m];
        }
#pragma unroll
        for (int off = 16; off > 0; off >>= 1)
            p += __shfl_xor_sync(0xffffffffu, p, off);
        if (lane == 0) s_e[warp] = p;
        __syncthreads();                                     // sync A

        // every warp computes identical softmax + gumbel-argmax
        float e = (lane < 16) ? s_e[lane] : -1e30f;
        float mx = e;
#pragma unroll
        for (int off = 8; off > 0; off >>= 1)
            mx = fmaxf(mx, __shfl_xor_sync(0xffffffffu, mx, off));
        float ex = expf(e - mx);
        float sm = ex;
#pragma unroll
        for (int off = 8; off > 0; off >>= 1)
            sm += __shfl_xor_sync(0xffffffffu, sm, off);
        float w = ex / sm;
        if (lane == 15) w += 10.0f;                          // null-slot bonus
        float z = (lane < 16) ? (w + s_g[t][lane]) : -1e30f;
        float bz = z; int bi = lane;
#pragma unroll
        for (int off = 8; off > 0; off >>= 1) {
            float oz = __shfl_xor_sync(0xffffffffu, bz, off);
            int   oi = __shfl_xor_sync(0xffffffffu, bi, off);
            if (oz > bz || (oz == bz && oi < bi)) { bz = oz; bi = oi; }
        }
        bi = __shfl_sync(0xffffffffu, bi, 0);
        int k = (bi < SLOTS && s_mask[t] != 0.f) ? bi : -1;

        if (warp == 0 && lane < 16)
            out_log[((size_t)b * NSTEP + t) * SSZ + lane] = (lane == bi) ? 1.f : 0.f;

        if (k >= 0) {   // rare write event: refresh memproj row k (exact fp32)
            s_tmp[tid] = states[((size_t)b * NSTEP + t) * MSZ + tid];
            if (tid == 0) s_lastwrite[k] = t;
            __syncthreads();
            float acc = 0.f;
            const float4* w4  = (const float4*)(attn_W + (size_t)tid * 1536 + 1024);
            const float4* st4 = (const float4*)s_tmp;
            for (int kk = 0; kk < MSZ / 4; kk++) {
                float4 ww = w4[kk]; float4 s = st4[kk];
                acc += ww.x * s.x + ww.y * s.y + ww.z * s.z + ww.w * s.w;
            }
            s_row[tid] = acc;
            __syncthreads();
            if (warp == k) {
#pragma unroll
                for (int i = 0; i < 16; i++) mp[i] = s_row[lane + 32 * i];
            }
        }

        if (t + 1 < NSTEP) s_q[1 - cur][tid] = qn + gadd;
        __syncthreads();                                     // sync B
    }

    for (int s = 0; s < SLOTS; s++) {
        int lw = s_lastwrite[s];
        const float* src = (lw >= 0)
            ? (states + ((size_t)b * NSTEP + lw) * MSZ)
            : (his_mem + ((size_t)b * SLOTS + s) * MSZ);
        out_hm[((size_t)b * SLOTS + s) * MSZ + tid] = src[tid];
    }
}

// ---------------------------------------------------------------------------
extern "C" void kernel_launch(void* const* d_in, const int* in_sizes, int n_in,
                              void* d_out, int out_size)
{
    const float* his_mem     = (const float*)d_in[0];
    const float* states      = (const float*)d_in[1];
    const float* states_mask = (const float*)d_in[2];
    const float* gt          = (const float*)d_in[3];
    const float* gumbel_u    = (const float*)d_in[5];
    const float* attn_W      = (const float*)d_in[6];
    const float* attn_b      = (const float*)d_in[7];
    const float* v           = (const float*)d_in[8];

    float* out     = (float*)d_out;
    float* out_hm  = out;                                   // [B,15,512]
    float* out_log = out + (size_t)BATCH * SLOTS * MSZ;     // [B,128,16]

    float *qproj = nullptr, *gproj = nullptr, *memproj = nullptr;
    cudaGetSymbolAddress((void**)&qproj, g_qproj);
    cudaGetSymbolAddress((void**)&gproj, g_gproj);
    cudaGetSymbolAddress((void**)&memproj, g_memproj);

    // one GEMM launch: qproj (256 tiles) + gproj (2) + memproj (30)
    dim3 grid(MSZ / 128, 256 + 2 + 30);
    tf32_gemm_all<<<grid, 256>>>(states, gt, his_mem, attn_W, attn_b,
                                 qproj, gproj, memproj);

    writer_kernel<<<BATCH, 512>>>(his_mem, states, states_mask, gumbel_u,
                                  attn_W, v, qproj, gproj, memproj,
                                  out_hm, out_log);
}

// round 8
// speedup vs baseline: 1.3678x; 1.0004x over previous
#include <cuda_runtime.h>
#include <math.h>
#include <stdint.h>

#define BATCH 256
#define NSTEP 128
#define MSZ   512
#define SLOTS 15
#define SSZ   16

// Scratch (no allocations allowed)
__device__ float g_qproj[(size_t)BATCH * NSTEP * MSZ];    // 64MB
__device__ float g_gproj[BATCH * MSZ];                    // 0.5MB
__device__ float g_memproj[BATCH * SLOTS * MSZ];          // 7.9MB

// ---------------------------------------------------------------------------
// TF32 helpers
// ---------------------------------------------------------------------------
__device__ __forceinline__ float f2tf(float x) {
    uint32_t r;
    asm("cvt.rna.tf32.f32 %0, %1;" : "=r"(r) : "f"(x));
    return __uint_as_float(r);
}

__device__ __forceinline__ void mma_tf32(float c[4],
                                         uint32_t a0, uint32_t a1,
                                         uint32_t a2, uint32_t a3,
                                         uint32_t b0, uint32_t b1) {
    asm volatile(
        "mma.sync.aligned.m16n8k8.row.col.f32.tf32.tf32.f32 "
        "{%0,%1,%2,%3}, {%4,%5,%6,%7}, {%8,%9}, {%0,%1,%2,%3};"
        : "+f"(c[0]), "+f"(c[1]), "+f"(c[2]), "+f"(c[3])
        : "r"(a0), "r"(a1), "r"(a2), "r"(a3), "r"(b0), "r"(b1));
}

// ---------------------------------------------------------------------------
// Unified split-TF32 GEMM. grid = (4, 288):
//   y <  256 : qproj rows  (X=states,  W+0,    out=g_qproj,   no addend)
//   y <  258 : gproj rows  (X=gt,      W+512,  out=g_gproj,   addend=bias)
//   y >= 258 : memproj rows(X=his_mem, W+1024, out=g_memproj, no addend)
// BM=BN=128, BK=32, 256 threads; hi/lo interleaved smem (stride 72).
// ---------------------------------------------------------------------------
#define BK 32
#define ASTR 72

__global__ __launch_bounds__(256) void tf32_gemm_all(
    const float* __restrict__ states,
    const float* __restrict__ gt,
    const float* __restrict__ his_mem,
    const float* __restrict__ W,
    const float* __restrict__ bias,
    float* __restrict__ qproj,
    float* __restrict__ gproj,
    float* __restrict__ memproj)
{
    __shared__ float sA[128 * ASTR];
    __shared__ float sB[128 * ASTR];

    int y = blockIdx.y;
    const float* X;
    const float* Wb;
    const float* addp = nullptr;
    float* outp;
    int r0;
    if (y < 256)      { X = states;  r0 = y * 128;         Wb = W;        outp = qproj; }
    else if (y < 258) { X = gt;      r0 = (y - 256) * 128; Wb = W + 512;  outp = gproj; addp = bias; }
    else              { X = his_mem; r0 = (y - 258) * 128; Wb = W + 1024; outp = memproj; }

    int tid  = threadIdx.x;
    int warp = tid >> 5, lane = tid & 31;
    int g    = lane >> 2, tig = lane & 3;
    int wm   = (warp >> 2) * 64;
    int wn   = (warp & 3) * 32;
    int n0   = blockIdx.x * 128;

    float acc[4][4][4];
#pragma unroll
    for (int a = 0; a < 4; a++)
#pragma unroll
        for (int b = 0; b < 4; b++)
#pragma unroll
            for (int c = 0; c < 4; c++) acc[a][b][c] = 0.f;

    int lr = tid >> 3;
    int kq = tid & 7;

    float4 pa[4], pb[4];
#pragma unroll
    for (int i = 0; i < 4; i++) {
        pa[i] = *(const float4*)&X[(size_t)(r0 + lr + 32 * i) * 512 + kq * 4];
        pb[i] = *(const float4*)&Wb[(size_t)(n0 + lr + 32 * i) * 1536 + kq * 4];
    }

    for (int t = 0; t < 512 / BK; t++) {
        __syncthreads();
#pragma unroll
        for (int i = 0; i < 4; i++) {
            float4 v = pa[i];
            float h0 = f2tf(v.x), h1 = f2tf(v.y), h2 = f2tf(v.z), h3 = f2tf(v.w);
            float4 s0 = {h0, f2tf(v.x - h0), h1, f2tf(v.y - h1)};
            float4 s1 = {h2, f2tf(v.z - h2), h3, f2tf(v.w - h3)};
            float* dst = &sA[(lr + 32 * i) * ASTR + kq * 8];
            *(float4*)dst = s0; *(float4*)(dst + 4) = s1;

            v = pb[i];
            h0 = f2tf(v.x); h1 = f2tf(v.y); h2 = f2tf(v.z); h3 = f2tf(v.w);
            float4 t0 = {h0, f2tf(v.x - h0), h1, f2tf(v.y - h1)};
            float4 t1 = {h2, f2tf(v.z - h2), h3, f2tf(v.w - h3)};
            dst = &sB[(lr + 32 * i) * ASTR + kq * 8];
            *(float4*)dst = t0; *(float4*)(dst + 4) = t1;
        }
        __syncthreads();

        if (t + 1 < 512 / BK) {
            int k0 = (t + 1) * BK;
#pragma unroll
            for (int i = 0; i < 4; i++) {
                pa[i] = *(const float4*)&X[(size_t)(r0 + lr + 32 * i) * 512 + k0 + kq * 4];
                pb[i] = *(const float4*)&Wb[(size_t)(n0 + lr + 32 * i) * 1536 + k0 + kq * 4];
            }
        }

#pragma unroll
        for (int k8 = 0; k8 < BK / 8; k8++) {
            uint32_t Ah[4][4], Al[4][4], Bh[4][2], Bl[4][2];
#pragma unroll
            for (int mf = 0; mf < 4; mf++) {
                int m0 = wm + mf * 16;
                float2 v0 = *(float2*)&sA[(m0 + g)     * ASTR + (k8 * 8 + tig)     * 2];
                float2 v1 = *(float2*)&sA[(m0 + g + 8) * ASTR + (k8 * 8 + tig)     * 2];
                float2 v2 = *(float2*)&sA[(m0 + g)     * ASTR + (k8 * 8 + tig + 4) * 2];
                float2 v3 = *(float2*)&sA[(m0 + g + 8) * ASTR + (k8 * 8 + tig + 4) * 2];
                Ah[mf][0] = __float_as_uint(v0.x); Al[mf][0] = __float_as_uint(v0.y);
                Ah[mf][1] = __float_as_uint(v1.x); Al[mf][1] = __float_as_uint(v1.y);
                Ah[mf][2] = __float_as_uint(v2.x); Al[mf][2] = __float_as_uint(v2.y);
                Ah[mf][3] = __float_as_uint(v3.x); Al[mf][3] = __float_as_uint(v3.y);
            }
#pragma unroll
            for (int nf = 0; nf < 4; nf++) {
                int n = wn + nf * 8 + g;
                float2 v0 = *(float2*)&sB[n * ASTR + (k8 * 8 + tig)     * 2];
                float2 v1 = *(float2*)&sB[n * ASTR + (k8 * 8 + tig + 4) * 2];
                Bh[nf][0] = __float_as_uint(v0.x); Bl[nf][0] = __float_as_uint(v0.y);
                Bh[nf][1] = __float_as_uint(v1.x); Bl[nf][1] = __float_as_uint(v1.y);
            }
#pragma unroll
            for (int mf = 0; mf < 4; mf++)
#pragma unroll
                for (int nf = 0; nf < 4; nf++) {
                    mma_tf32(acc[mf][nf], Ah[mf][0], Ah[mf][1], Ah[mf][2], Ah[mf][3],
                             Bh[nf][0], Bh[nf][1]);
                    mma_tf32(acc[mf][nf], Ah[mf][0], Ah[mf][1], Ah[mf][2], Ah[mf][3],
                             Bl[nf][0], Bl[nf][1]);
                    mma_tf32(acc[mf][nf], Al[mf][0], Al[mf][1], Al[mf][2], Al[mf][3],
                             Bh[nf][0], Bh[nf][1]);
                }
        }
    }

#pragma unroll
    for (int mf = 0; mf < 4; mf++)
#pragma unroll
        for (int nf = 0; nf < 4; nf++) {
            int col_l = wn + nf * 8 + 2 * tig;
            int col   = n0 + col_l;
            int row   = r0 + wm + mf * 16 + g;
            float a0 = 0.f, a1 = 0.f;
            if (addp) { a0 = addp[col]; a1 = addp[col + 1]; }
            float2 s0 = {acc[mf][nf][0] + a0, acc[mf][nf][1] + a1};
            float2 s1 = {acc[mf][nf][2] + a0, acc[mf][nf][3] + a1};
            *(float2*)&outp[(size_t)row * MSZ + col]       = s0;
            *(float2*)&outp[(size_t)(row + 8) * MSZ + col] = s1;
        }
}

// ---------------------------------------------------------------------------
// Exact-enough branch-free tanh: 1 - 2*rcp(exp2(2*log2(e)*x) + 1).
// abs err ~2.4e-7 (ex2/rcp approx ~1-2 ulp) — 100x inside decision margins.
// ---------------------------------------------------------------------------
__device__ __forceinline__ float tanh_acc(float x) {
    float e;
    asm("ex2.approx.f32 %0, %1;" : "=f"(e) : "f"(x * 2.88539008177793f));
    float r;
    asm("rcp.approx.f32 %0, %1;" : "=f"(r) : "f"(e + 1.0f));
    return fmaf(-2.0f, r, 1.0f);
}

// ---------------------------------------------------------------------------
// Sequential writer. One block per batch, 16 warps, warp s owns slot s.
// memproj rows come precomputed from the GEMM; gumbel noise + masks
// precomputed once; q row double-buffered with register prefetch; redundant
// softmax/argmax in every warp (bit-identical) -> 2 syncs per step.
// ---------------------------------------------------------------------------
__global__ __launch_bounds__(512, 2) void writer_kernel(
    const float* __restrict__ his_mem,
    const float* __restrict__ states,
    const float* __restrict__ states_mask,
    const float* __restrict__ gumbel_u,
    const float* __restrict__ attn_W,
    const float* __restrict__ v,
    const float* __restrict__ qproj,
    const float* __restrict__ gproj,
    const float* __restrict__ memproj,
    float* __restrict__ out_hm,
    float* __restrict__ out_log)
{
    __shared__ float s_q[2][MSZ];
    __shared__ float s_v[MSZ];
    __shared__ float s_g[NSTEP][SSZ];
    __shared__ float s_mask[NSTEP];
    __shared__ float s_e[SSZ];
    __shared__ float s_tmp[MSZ];
    __shared__ float s_row[MSZ];
    __shared__ int   s_lastwrite[SLOTS];

    int b    = blockIdx.x;
    int tid  = threadIdx.x;
    int lane = tid & 31;
    int warp = tid >> 5;

    s_v[tid] = v[tid];
    if (tid < SLOTS) s_lastwrite[tid] = -1;
    if (tid < NSTEP) s_mask[tid] = states_mask[b * NSTEP + tid];
    {
        float4 u4 = *(const float4*)(gumbel_u + (size_t)b * NSTEP * SSZ + tid * 4);
        float uu[4] = {u4.x, u4.y, u4.z, u4.w};
        float gg[4];
#pragma unroll
        for (int i = 0; i < 4; i++) {
            float u = fminf(fmaxf(uu[i], 1e-20f), 1.0f);
            gg[i] = -logf(-logf(u) + 1e-20f);
        }
        *(float4*)(&s_g[0][0] + tid * 4) = make_float4(gg[0], gg[1], gg[2], gg[3]);
    }

    float gadd = gproj[b * MSZ + tid];
    float mp[16];
#pragma unroll
    for (int i = 0; i < 16; i++)
        mp[i] = (warp < SLOTS)
              ? memproj[((size_t)b * SLOTS + warp) * MSZ + lane + 32 * i] : 0.f;

    const float* qrow = qproj + (size_t)b * NSTEP * MSZ;
    s_q[0][tid] = qrow[tid] + gadd;
    __syncthreads();

    for (int t = 0; t < NSTEP; t++) {
        int cur = t & 1;
        float qn = 0.f;
        if (t + 1 < NSTEP) qn = qrow[(t + 1) * MSZ + tid];   // prefetch

        float p = 0.f;
#pragma unroll
        for (int i = 0; i < 16; i++) {
            int m = lane + 32 * i;
            p += tanh_acc(s_q[cur][m] + mp[i]) * s_v[m];
        }
#pragma unroll
        for (int off = 16; off > 0; off >>= 1)
            p += __shfl_xor_sync(0xffffffffu, p, off);
        if (lane == 0) s_e[warp] = p;
        __syncthreads();                                     // sync A

        // every warp computes identical softmax + gumbel-argmax
        float e = (lane < 16) ? s_e[lane] : -1e30f;
        float mx = e;
#pragma unroll
        for (int off = 8; off > 0; off >>= 1)
            mx = fmaxf(mx, __shfl_xor_sync(0xffffffffu, mx, off));
        float ex = expf(e - mx);
        float sm = ex;
#pragma unroll
        for (int off = 8; off > 0; off >>= 1)
            sm += __shfl_xor_sync(0xffffffffu, sm, off);
        float w = ex / sm;
        if (lane == 15) w += 10.0f;                          // null-slot bonus
        float z = (lane < 16) ? (w + s_g[t][lane]) : -1e30f;
        float bz = z; int bi = lane;
#pragma unroll
        for (int off = 8; off > 0; off >>= 1) {
            float oz = __shfl_xor_sync(0xffffffffu, bz, off);
            int   oi = __shfl_xor_sync(0xffffffffu, bi, off);
            if (oz > bz || (oz == bz && oi < bi)) { bz = oz; bi = oi; }
        }
        bi = __shfl_sync(0xffffffffu, bi, 0);
        int k = (bi < SLOTS && s_mask[t] != 0.f) ? bi : -1;

        if (warp == 0 && lane < 16)
            out_log[((size_t)b * NSTEP + t) * SSZ + lane] = (lane == bi) ? 1.f : 0.f;

        if (k >= 0) {   // rare write event: refresh memproj row k (exact fp32)
            s_tmp[tid] = states[((size_t)b * NSTEP + t) * MSZ + tid];
            if (tid == 0) s_lastwrite[k] = t;
            __syncthreads();
            float acc = 0.f;
            const float4* w4  = (const float4*)(attn_W + (size_t)tid * 1536 + 1024);
            const float4* st4 = (const float4*)s_tmp;
            for (int kk = 0; kk < MSZ / 4; kk++) {
                float4 ww = w4[kk]; float4 s = st4[kk];
                acc += ww.x * s.x + ww.y * s.y + ww.z * s.z + ww.w * s.w;
            }
            s_row[tid] = acc;
            __syncthreads();
            if (warp == k) {
#pragma unroll
                for (int i = 0; i < 16; i++) mp[i] = s_row[lane + 32 * i];
            }
        }

        if (t + 1 < NSTEP) s_q[1 - cur][tid] = qn + gadd;
        __syncthreads();                                     // sync B
    }

    for (int s = 0; s < SLOTS; s++) {
        int lw = s_lastwrite[s];
        const float* src = (lw >= 0)
            ? (states + ((size_t)b * NSTEP + lw) * MSZ)
            : (his_mem + ((size_t)b * SLOTS + s) * MSZ);
        out_hm[((size_t)b * SLOTS + s) * MSZ + tid] = src[tid];
    }
}

// ---------------------------------------------------------------------------
extern "C" void kernel_launch(void* const* d_in, const int* in_sizes, int n_in,
                              void* d_out, int out_size)
{
    const float* his_mem     = (const float*)d_in[0];
    const float* states      = (const float*)d_in[1];
    const float* states_mask = (const float*)d_in[2];
    const float* gt          = (const float*)d_in[3];
    const float* gumbel_u    = (const float*)d_in[5];
    const float* attn_W      = (const float*)d_in[6];
    const float* attn_b      = (const float*)d_in[7];
    const float* v           = (const float*)d_in[8];

    float* out     = (float*)d_out;
    float* out_hm  = out;                                   // [B,15,512]
    float* out_log = out + (size_t)BATCH * SLOTS * MSZ;     // [B,128,16]

    float *qproj = nullptr, *gproj = nullptr, *memproj = nullptr;
    cudaGetSymbolAddress((void**)&qproj, g_qproj);
    cudaGetSymbolAddress((void**)&gproj, g_gproj);
    cudaGetSymbolAddress((void**)&memproj, g_memproj);

    // one GEMM launch: qproj (256 tiles) + gproj (2) + memproj (30)
    dim3 grid(MSZ / 128, 256 + 2 + 30);
    tf32_gemm_all<<<grid, 256>>>(states, gt, his_mem, attn_W, attn_b,
                                 qproj, gproj, memproj);

    writer_kernel<<<BATCH, 512>>>(his_mem, states, states_mask, gumbel_u,
                                  attn_W, v, qproj, gproj, memproj,
                                  out_hm, out_log);
}